// round 2
// baseline (speedup 1.0000x reference)
#include <cuda_runtime.h>

// Problem constants
#define Dc 128
#define TE 64
#define NTHREADS 256
#define NN 50000
#define EE 500000
#define MAXT 10.0f

// Scratch (device globals: no allocation allowed)
__device__ float g_agg[(size_t)NN * Dc];   // segment_sum of edge_feat by row
__device__ float g_csum[(size_t)NN * 3];   // segment sum of trans by row
__device__ float g_deg[NN];                // edge count per row

__device__ __forceinline__ float sigmoidf_(float x) { return 1.f / (1.f + __expf(-x)); }
__device__ __forceinline__ float siluf_(float x) { return x / (1.f + __expf(-x)); }
__device__ __forceinline__ float clampt_(float x) { return fminf(fmaxf(x, -MAXT), MAXT); }

__global__ void zero_kernel() {
    const int total = NN * Dc + NN * 3 + NN;
    for (int i = blockIdx.x * blockDim.x + threadIdx.x; i < total; i += gridDim.x * blockDim.x) {
        if (i < NN * Dc) g_agg[i] = 0.f;
        else if (i < NN * Dc + NN * 3) g_csum[i - NN * Dc] = 0.f;
        else g_deg[i - NN * Dc - NN * 3] = 0.f;
    }
}

// acc[e] over 8 edges x 4 features; Xs is [TE][Dc] smem tile; W is row-major [128 x Dc]
// Thread layout: tx = lane (features 4*tx..4*tx+3), ty = warp (edges 8*ty..8*ty+7)
__device__ __forceinline__ void gemm128(const float* __restrict__ W,
                                        const float (*Xs)[Dc],
                                        int ty, int tx, float4 acc[8]) {
    const float* wp = W + 4 * tx;
#pragma unroll 1
    for (int k = 0; k < Dc; k += 4) {
        float4 w0 = __ldg((const float4*)(wp + (k + 0) * Dc));
        float4 w1 = __ldg((const float4*)(wp + (k + 1) * Dc));
        float4 w2 = __ldg((const float4*)(wp + (k + 2) * Dc));
        float4 w3 = __ldg((const float4*)(wp + (k + 3) * Dc));
#pragma unroll
        for (int e = 0; e < 8; e++) {
            float4 x = *(const float4*)&Xs[ty * 8 + e][k];
            acc[e].x += x.x * w0.x + x.y * w1.x + x.z * w2.x + x.w * w3.x;
            acc[e].y += x.x * w0.y + x.y * w1.y + x.z * w2.y + x.w * w3.y;
            acc[e].z += x.x * w0.z + x.y * w1.z + x.z * w2.z + x.w * w3.z;
            acc[e].w += x.x * w0.w + x.y * w1.w + x.z * w2.w + x.w * w3.w;
        }
    }
}

__device__ __forceinline__ float warp_sum(float p) {
#pragma unroll
    for (int off = 16; off > 0; off >>= 1) p += __shfl_xor_sync(0xffffffffu, p, off);
    return p;
}

__global__ void __launch_bounds__(NTHREADS) edge_kernel(
    const float* __restrict__ h, const int* __restrict__ ei, const float* __restrict__ coord,
    const float* __restrict__ We1, const float* __restrict__ be1,
    const float* __restrict__ We2, const float* __restrict__ be2,
    const float* __restrict__ Watt, const float* __restrict__ batt,
    const float* __restrict__ Wc1, const float* __restrict__ bc1,
    const float* __restrict__ Wc2, float* __restrict__ edge_out) {
    __shared__ float Xs[TE][Dc];
    __shared__ int sRow[TE];
    __shared__ int sCol[TE];
    __shared__ float sRad[TE];
    __shared__ float sCd[TE][3];

    const int tid = threadIdx.x;
    const int tx = tid & 31;
    const int ty = tid >> 5;
    const int base = blockIdx.x * TE;

    if (tid < TE) {
        int ee = base + tid;
        if (ee >= EE) ee = EE - 1;  // clamp; writes masked later
        int r = ei[ee];
        int c = ei[EE + ee];
        sRow[tid] = r;
        sCol[tid] = c;
        float dx = coord[r * 3 + 0] - coord[c * 3 + 0];
        float dy = coord[r * 3 + 1] - coord[c * 3 + 1];
        float dz = coord[r * 3 + 2] - coord[c * 3 + 2];
        sCd[tid][0] = dx; sCd[tid][1] = dy; sCd[tid][2] = dz;
        sRad[tid] = dx * dx + dy * dy + dz * dz;
    }
    __syncthreads();

    // ---- stage h[row] tile, GEMM with We1 rows [0,128) ----
    for (int i = tid; i < TE * 32; i += NTHREADS) {
        int e = i >> 5, l = i & 31;
        *(float4*)&Xs[e][l * 4] = __ldg((const float4*)&h[(size_t)sRow[e] * Dc + l * 4]);
    }
    __syncthreads();

    float4 acc[8];
#pragma unroll
    for (int e = 0; e < 8; e++) acc[e] = make_float4(0.f, 0.f, 0.f, 0.f);
    gemm128(We1, Xs, ty, tx, acc);
    __syncthreads();

    // ---- stage h[col] tile, GEMM with We1 rows [128,256) ----
    for (int i = tid; i < TE * 32; i += NTHREADS) {
        int e = i >> 5, l = i & 31;
        *(float4*)&Xs[e][l * 4] = __ldg((const float4*)&h[(size_t)sCol[e] * Dc + l * 4]);
    }
    __syncthreads();
    gemm128(We1 + 128 * Dc, Xs, ty, tx, acc);

    // radial term (We1 row 256) + bias + SiLU
    {
        float4 wr = __ldg((const float4*)&We1[256 * Dc + 4 * tx]);
        float4 b1 = __ldg((const float4*)&be1[4 * tx]);
#pragma unroll
        for (int e = 0; e < 8; e++) {
            float rad = sRad[ty * 8 + e];
            acc[e].x = siluf_(acc[e].x + rad * wr.x + b1.x);
            acc[e].y = siluf_(acc[e].y + rad * wr.y + b1.y);
            acc[e].z = siluf_(acc[e].z + rad * wr.z + b1.z);
            acc[e].w = siluf_(acc[e].w + rad * wr.w + b1.w);
        }
    }
    __syncthreads();
#pragma unroll
    for (int e = 0; e < 8; e++) *(float4*)&Xs[ty * 8 + e][4 * tx] = acc[e];
    __syncthreads();

    // ---- e2 = silu(e1 @ We2 + be2); att; edge_feat = e2 * att ----
#pragma unroll
    for (int e = 0; e < 8; e++) acc[e] = make_float4(0.f, 0.f, 0.f, 0.f);
    gemm128(We2, Xs, ty, tx, acc);
    {
        float4 b2 = __ldg((const float4*)&be2[4 * tx]);
        float4 wa = __ldg((const float4*)&Watt[4 * tx]);
        float ba = __ldg(batt);
#pragma unroll
        for (int e = 0; e < 8; e++) {
            acc[e].x = siluf_(acc[e].x + b2.x);
            acc[e].y = siluf_(acc[e].y + b2.y);
            acc[e].z = siluf_(acc[e].z + b2.z);
            acc[e].w = siluf_(acc[e].w + b2.w);
            float p = acc[e].x * wa.x + acc[e].y * wa.y + acc[e].z * wa.z + acc[e].w * wa.w;
            p = warp_sum(p);
            float att = sigmoidf_(p + ba);
            acc[e].x *= att; acc[e].y *= att; acc[e].z *= att; acc[e].w *= att;
        }
    }
    __syncthreads();

    // ---- write edge_feat + segment_sum atomics; stage tile for coord MLP ----
#pragma unroll
    for (int e = 0; e < 8; e++) {
        int le = ty * 8 + e;
        *(float4*)&Xs[le][4 * tx] = acc[e];
        int ee = base + le;
        if (ee < EE) {
            *(float4*)&edge_out[(size_t)ee * Dc + 4 * tx] = acc[e];
            float* ag = &g_agg[(size_t)sRow[le] * Dc + 4 * tx];
            atomicAdd(ag + 0, acc[e].x);
            atomicAdd(ag + 1, acc[e].y);
            atomicAdd(ag + 2, acc[e].z);
            atomicAdd(ag + 3, acc[e].w);
        }
    }
    __syncthreads();

    // ---- coord MLP: cw = silu(edge_feat @ Wc1 + bc1) @ Wc2 ----
#pragma unroll
    for (int e = 0; e < 8; e++) acc[e] = make_float4(0.f, 0.f, 0.f, 0.f);
    gemm128(Wc1, Xs, ty, tx, acc);
    {
        float4 bc = __ldg((const float4*)&bc1[4 * tx]);
        float4 w2 = __ldg((const float4*)&Wc2[4 * tx]);
#pragma unroll
        for (int e = 0; e < 8; e++) {
            float a0 = siluf_(acc[e].x + bc.x);
            float a1 = siluf_(acc[e].y + bc.y);
            float a2 = siluf_(acc[e].z + bc.z);
            float a3 = siluf_(acc[e].w + bc.w);
            float p = a0 * w2.x + a1 * w2.y + a2 * w2.z + a3 * w2.w;
            float cw = warp_sum(p);  // all lanes hold cw
            int le = ty * 8 + e;
            int ee = base + le;
            if (ee < EE) {
                if (tx < 3) {
                    float t = clampt_(sCd[le][tx] * cw);
                    atomicAdd(&g_csum[(size_t)sRow[le] * 3 + tx], t);
                } else if (tx == 3) {
                    atomicAdd(&g_deg[sRow[le]], 1.f);
                }
            }
        }
    }
}

__global__ void __launch_bounds__(NTHREADS) node_kernel(
    const float* __restrict__ h, const float* __restrict__ coord,
    const float* __restrict__ Wn1, const float* __restrict__ bn1,
    const float* __restrict__ Wn2, const float* __restrict__ bn2,
    float* __restrict__ hout, float* __restrict__ cout) {
    __shared__ float Xs[TE][Dc];
    const int tid = threadIdx.x;
    const int tx = tid & 31;
    const int ty = tid >> 5;
    const int base = blockIdx.x * TE;

    // stage h tile (clamped)
    for (int i = tid; i < TE * 32; i += NTHREADS) {
        int n = base + (i >> 5);
        if (n >= NN) n = NN - 1;
        *(float4*)&Xs[i >> 5][(i & 31) * 4] = __ldg((const float4*)&h[(size_t)n * Dc + (i & 31) * 4]);
    }
    __syncthreads();

    float4 acc[8];
#pragma unroll
    for (int e = 0; e < 8; e++) acc[e] = make_float4(0.f, 0.f, 0.f, 0.f);
    gemm128(Wn1, Xs, ty, tx, acc);  // rows [0,128): h part
    __syncthreads();

    // stage agg tile
    for (int i = tid; i < TE * 32; i += NTHREADS) {
        int n = base + (i >> 5);
        if (n >= NN) n = NN - 1;
        *(float4*)&Xs[i >> 5][(i & 31) * 4] = *(const float4*)&g_agg[(size_t)n * Dc + (i & 31) * 4];
    }
    __syncthreads();
    gemm128(Wn1 + 128 * Dc, Xs, ty, tx, acc);  // rows [128,256): agg part

    {
        float4 b1 = __ldg((const float4*)&bn1[4 * tx]);
#pragma unroll
        for (int e = 0; e < 8; e++) {
            acc[e].x = siluf_(acc[e].x + b1.x);
            acc[e].y = siluf_(acc[e].y + b1.y);
            acc[e].z = siluf_(acc[e].z + b1.z);
            acc[e].w = siluf_(acc[e].w + b1.w);
        }
    }
    __syncthreads();
#pragma unroll
    for (int e = 0; e < 8; e++) *(float4*)&Xs[ty * 8 + e][4 * tx] = acc[e];
    __syncthreads();

#pragma unroll
    for (int e = 0; e < 8; e++) acc[e] = make_float4(0.f, 0.f, 0.f, 0.f);
    gemm128(Wn2, Xs, ty, tx, acc);
    {
        float4 b2 = __ldg((const float4*)&bn2[4 * tx]);
#pragma unroll
        for (int e = 0; e < 8; e++) {
            int n = base + ty * 8 + e;
            if (n < NN) {
                float4 hr = __ldg((const float4*)&h[(size_t)n * Dc + 4 * tx]);
                float4 o;
                o.x = hr.x + acc[e].x + b2.x;
                o.y = hr.y + acc[e].y + b2.y;
                o.z = hr.z + acc[e].z + b2.z;
                o.w = hr.w + acc[e].w + b2.w;
                *(float4*)&hout[(size_t)n * Dc + 4 * tx] = o;
            }
        }
    }

    // coord output: 64 nodes x 3 components
    if (tid < TE * 3) {
        int e = tid / 3, c = tid % 3;
        int n = base + e;
        if (n < NN) {
            float d = fmaxf(g_deg[n], 1.f);
            float v = clampt_(g_csum[(size_t)n * 3 + c] / d);
            cout[(size_t)n * 3 + c] = coord[(size_t)n * 3 + c] + v;
        }
    }
}

extern "C" void kernel_launch(void* const* d_in, const int* in_sizes, int n_in,
                              void* d_out, int out_size) {
    const float* h     = (const float*)d_in[0];
    const int*   ei    = (const int*)d_in[1];   // jax x64 disabled -> int32
    const float* coord = (const float*)d_in[2];
    const float* We1   = (const float*)d_in[3];
    const float* be1   = (const float*)d_in[4];
    const float* We2   = (const float*)d_in[5];
    const float* be2   = (const float*)d_in[6];
    const float* Watt  = (const float*)d_in[7];
    const float* batt  = (const float*)d_in[8];
    const float* Wc1   = (const float*)d_in[9];
    const float* bc1   = (const float*)d_in[10];
    const float* Wc2   = (const float*)d_in[11];
    const float* Wn1   = (const float*)d_in[12];
    const float* bn1   = (const float*)d_in[13];
    const float* Wn2   = (const float*)d_in[14];
    const float* bn2   = (const float*)d_in[15];

    float* out  = (float*)d_out;
    float* hout = out;                                   // [N,128]
    float* cout = out + (size_t)NN * Dc;                 // [N,3]
    float* eout = cout + (size_t)NN * 3;                 // [E,128]

    zero_kernel<<<2048, 256>>>();
    edge_kernel<<<(EE + TE - 1) / TE, NTHREADS>>>(h, ei, coord, We1, be1, We2, be2,
                                                  Watt, batt, Wc1, bc1, Wc2, eout);
    node_kernel<<<(NN + TE - 1) / TE, NTHREADS>>>(h, coord, Wn1, bn1, Wn2, bn2, hout, cout);
}